// round 1
// baseline (speedup 1.0000x reference)
#include <cuda_runtime.h>
#include <math.h>

#define N_   4
#define K_   8
#define H_   512
#define W_   512
#define C_   16
#define P_   1000000
#define HW_  (H_ * W_)
#define NPIX (N_ * HW_)

// Transposed point cloud: [P][C], 64B per point (aligned) so each fragment's
// 16 channel values are one contiguous 64B read (2 L2 sectors) instead of
// 16 scattered 4B reads (16 sectors). 64 MB — fits in the 126 MB L2.
__device__ __align__(16) float g_pt_t[(size_t)P_ * C_];

// ---------------------------------------------------------------------------
// Kernel 1: transpose ptclds [C, P] -> g_pt_t [P, C]
// Reads are fully coalesced (fixed c, consecutive p across lanes).
// Writes: each lane stores 4x float4 into its own 64B block; every 32B sector
// of the warp's 2KB output region is written exactly once.
// ---------------------------------------------------------------------------
__global__ void transpose_ptclds_kernel(const float* __restrict__ pt) {
    int p = blockIdx.x * blockDim.x + threadIdx.x;
    if (p >= P_) return;
    float4* dst = reinterpret_cast<float4*>(g_pt_t) + (size_t)p * 4;
#pragma unroll
    for (int j = 0; j < 4; j++) {
        float4 v;
        v.x = __ldg(pt + (size_t)(j * 4 + 0) * P_ + p);
        v.y = __ldg(pt + (size_t)(j * 4 + 1) * P_ + p);
        v.z = __ldg(pt + (size_t)(j * 4 + 2) * P_ + p);
        v.w = __ldg(pt + (size_t)(j * 4 + 3) * P_ + p);
        dst[j] = v;
    }
}

// ---------------------------------------------------------------------------
// Kernel 2: softmax over K + gather + composite.
// One thread per pixel (n, h, w).
// ---------------------------------------------------------------------------
__global__ void __launch_bounds__(256)
compositor_kernel(const int* __restrict__ frag,
                  const float* __restrict__ zbuf,
                  float* __restrict__ out) {
    int i = blockIdx.x * blockDim.x + threadIdx.x;
    if (i >= NPIX) return;

    int n  = i / HW_;
    int hw = i - n * HW_;
    size_t base = (size_t)n * K_ * HW_ + hw;

    // Load all K fragments + z values (coalesced per k across the warp).
    int   fr[K_];
    float imp[K_];
    float m = -INFINITY;
#pragma unroll
    for (int k = 0; k < K_; k++) {
        float z = zbuf[base + (size_t)k * HW_];
        fr[k]   = frag[base + (size_t)k * HW_];
        if (z < 0.0f) z = -0.0001f;
        imp[k] = 1.0f / (z + 1e-6f);
        m = fmaxf(m, imp[k]);
    }

    // Stable softmax over K (importance can reach 1e6 -> must subtract max).
    float s = 0.0f;
#pragma unroll
    for (int k = 0; k < K_; k++) {
        imp[k] = expf(imp[k] - m);
        s += imp[k];
    }
    float inv = 1.0f / s;

    // Gather 16 channels per fragment (one 64B contiguous read each) and
    // accumulate. 8 independent gathers x 4 float4 = high MLP.
    float acc[C_];
#pragma unroll
    for (int c = 0; c < C_; c++) acc[c] = 0.0f;

#pragma unroll
    for (int k = 0; k < K_; k++) {
        float w = imp[k] * inv;
        const float4* pp = reinterpret_cast<const float4*>(g_pt_t)
                         + (size_t)fr[k] * 4;
#pragma unroll
        for (int j = 0; j < 4; j++) {
            float4 v = __ldg(pp + j);
            acc[j * 4 + 0] = fmaf(w, v.x, acc[j * 4 + 0]);
            acc[j * 4 + 1] = fmaf(w, v.y, acc[j * 4 + 1]);
            acc[j * 4 + 2] = fmaf(w, v.z, acc[j * 4 + 2]);
            acc[j * 4 + 3] = fmaf(w, v.w, acc[j * 4 + 3]);
        }
    }

    // Write out[n][c][h][w]; for fixed c, lanes write consecutive addresses.
    size_t ob = (size_t)n * C_ * HW_ + hw;
#pragma unroll
    for (int c = 0; c < C_; c++) {
        out[ob + (size_t)c * HW_] = acc[c];
    }
}

extern "C" void kernel_launch(void* const* d_in, const int* in_sizes, int n_in,
                              void* d_out, int out_size) {
    const int*   fragments = (const int*)d_in[0];
    const float* zbuf      = (const float*)d_in[1];
    const float* ptclds    = (const float*)d_in[2];
    float*       out       = (float*)d_out;

    (void)in_sizes; (void)n_in; (void)out_size;

    // 1) Transpose point cloud into L2-resident scratch.
    {
        int threads = 256;
        int blocks  = (P_ + threads - 1) / threads;
        transpose_ptclds_kernel<<<blocks, threads>>>(ptclds);
    }
    // 2) Softmax + gather + composite.
    {
        int threads = 256;
        int blocks  = (NPIX + threads - 1) / threads;
        compositor_kernel<<<blocks, threads>>>(fragments, zbuf, out);
    }
}

// round 2
// speedup vs baseline: 1.7840x; 1.7840x over previous
#include <cuda_runtime.h>
#include <math.h>

#define N_   4
#define K_   8
#define H_   512
#define W_   512
#define C_   16
#define P_   1000000
#define HW_  (H_ * W_)
#define NPIX (N_ * HW_)

// Transposed point cloud: [P][C], 64B per point so a whole point's 16 channels
// are one contiguous 64B read (2 L2 sectors). 64 MB - resident in the 126MB L2.
__device__ __align__(16) float g_pt_t[(size_t)P_ * C_];

// ---------------------------------------------------------------------------
// Kernel 1: transpose ptclds [C, P] -> g_pt_t [P, C]
// ---------------------------------------------------------------------------
__global__ void transpose_ptclds_kernel(const float* __restrict__ pt) {
    int p = blockIdx.x * blockDim.x + threadIdx.x;
    if (p >= P_) return;
    float4* dst = reinterpret_cast<float4*>(g_pt_t) + (size_t)p * 4;
#pragma unroll
    for (int j = 0; j < 4; j++) {
        float4 v;
        v.x = __ldcs(pt + (size_t)(j * 4 + 0) * P_ + p);
        v.y = __ldcs(pt + (size_t)(j * 4 + 1) * P_ + p);
        v.z = __ldcs(pt + (size_t)(j * 4 + 2) * P_ + p);
        v.w = __ldcs(pt + (size_t)(j * 4 + 3) * P_ + p);
        dst[j] = v;
    }
}

// ---------------------------------------------------------------------------
// Kernel 2: quad-per-pixel compositor.
// 4 lanes cooperate on one pixel: lane j owns channels [4j, 4j+4).
// Gather: per warp per k, ONE LDG.128 touches 8 distinct 64B points
// (8 L1 wavefronts) instead of 32 lines x 4 instructions (128 wavefronts).
// ---------------------------------------------------------------------------
__global__ void __launch_bounds__(256)
compositor_kernel(const int* __restrict__ frag,
                  const float* __restrict__ zbuf,
                  float* __restrict__ out) {
    __shared__ float s_out[64 * 17];   // [pixel][channel], pad 17 -> conflict-free read

    int tid = threadIdx.x;
    int q   = tid >> 2;                // block-local pixel 0..63
    int j   = tid & 3;                 // quad lane (channel group)

    int i  = blockIdx.x * 64 + q;      // global pixel; HW_ % 64 == 0 -> no n straddle
    int n  = i / HW_;
    int hw = i - n * HW_;
    size_t base = (size_t)n * K_ * HW_ + hw;

    // --- distributed softmax: lane j handles k = 2j, 2j+1 ---
    float z0 = __ldcs(zbuf + base + (size_t)(2 * j)     * HW_);
    float z1 = __ldcs(zbuf + base + (size_t)(2 * j + 1) * HW_);
    if (z0 < 0.0f) z0 = -0.0001f;
    if (z1 < 0.0f) z1 = -0.0001f;
    float i0 = 1.0f / (z0 + 1e-6f);
    float i1 = 1.0f / (z1 + 1e-6f);

    float m = fmaxf(i0, i1);
    m = fmaxf(m, __shfl_xor_sync(0xffffffffu, m, 1));
    m = fmaxf(m, __shfl_xor_sync(0xffffffffu, m, 2));

    float e0 = __expf(i0 - m);
    float e1 = __expf(i1 - m);
    float s  = e0 + e1;
    s += __shfl_xor_sync(0xffffffffu, s, 1);
    s += __shfl_xor_sync(0xffffffffu, s, 2);
    float inv = 1.0f / s;
    float w0 = e0 * inv;               // weight for k = 2j
    float w1 = e1 * inv;               // weight for k = 2j+1

    // --- fragment indices (broadcast within quad, coalesced across pixels) ---
    int fr[K_];
#pragma unroll
    for (int k = 0; k < K_; k++)
        fr[k] = __ldcs(frag + base + (size_t)k * HW_);

    // --- cooperative gather + weighted accumulate ---
    float4 acc = make_float4(0.f, 0.f, 0.f, 0.f);
#pragma unroll
    for (int k = 0; k < K_; k++) {
        int   src = (tid & ~3) | (k >> 1);                       // quad lane owning w[k]
        float wk  = __shfl_sync(0xffffffffu, (k & 1) ? w1 : w0, src);
        const float4* pp = reinterpret_cast<const float4*>(
                               g_pt_t + (size_t)fr[k] * C_) + j;
        float4 v = __ldg(pp);
        acc.x = fmaf(wk, v.x, acc.x);
        acc.y = fmaf(wk, v.y, acc.y);
        acc.z = fmaf(wk, v.z, acc.z);
        acc.w = fmaf(wk, v.w, acc.w);
    }

    // --- stage to smem, then coalesced global stores ---
    float* sp = s_out + q * 17 + j * 4;
    sp[0] = acc.x; sp[1] = acc.y; sp[2] = acc.z; sp[3] = acc.w;
    __syncthreads();

    int hw_base = hw - q;                              // block's first hw
    size_t ob = (size_t)n * C_ * HW_ + hw_base;
#pragma unroll
    for (int r = 0; r < 4; r++) {
        int idx = r * 256 + tid;                       // 0..1023
        int c   = idx >> 6;                            // channel
        int px  = idx & 63;                            // block-local pixel
        __stcs(out + ob + (size_t)c * HW_ + px, s_out[px * 17 + c]);
    }
}

extern "C" void kernel_launch(void* const* d_in, const int* in_sizes, int n_in,
                              void* d_out, int out_size) {
    const int*   fragments = (const int*)d_in[0];
    const float* zbuf      = (const float*)d_in[1];
    const float* ptclds    = (const float*)d_in[2];
    float*       out       = (float*)d_out;

    (void)in_sizes; (void)n_in; (void)out_size;

    {
        int threads = 256;
        int blocks  = (P_ + threads - 1) / threads;
        transpose_ptclds_kernel<<<blocks, threads>>>(ptclds);
    }
    {
        int threads = 256;
        int blocks  = NPIX / 64;       // 64 pixels per block (quad-per-pixel)
        compositor_kernel<<<blocks, threads>>>(fragments, zbuf, out);
    }
}

// round 4
// speedup vs baseline: 2.2917x; 1.2846x over previous
#include <cuda_runtime.h>
#include <cuda_fp16.h>
#include <math.h>
#include <cstdint>

#define N_   4
#define K_   8
#define H_   512
#define W_   512
#define C_   16
#define P_   1000000
#define HW_  (H_ * W_)
#define NPIX (N_ * HW_)

// Transposed fp16 point cloud: [P][C], 32B per point. 32 MB -> fully L2
// resident (126 MB L2) even with streaming traffic. One point's 16 channels
// = one 32B sector.
__device__ __align__(16) __half g_pt_h[(size_t)P_ * C_];

// ---------------------------------------------------------------------------
// Kernel 1: transpose + fp16-convert ptclds [C, P] -> g_pt_h [P, C]
// Reads coalesced (fixed c, consecutive p across lanes); each thread packs
// its point into 2x 16B stores.
// ---------------------------------------------------------------------------
__global__ void transpose_ptclds_kernel(const float* __restrict__ pt) {
    int p = blockIdx.x * blockDim.x + threadIdx.x;
    if (p >= P_) return;
    uint4* dst = reinterpret_cast<uint4*>(g_pt_h + (size_t)p * C_);
#pragma unroll
    for (int hh = 0; hh < 2; hh++) {          // 8 channels per 16B store
        uint4 o;
        unsigned int* ow = reinterpret_cast<unsigned int*>(&o);
#pragma unroll
        for (int j = 0; j < 4; j++) {
            int c0 = hh * 8 + j * 2;
            float a = __ldcs(pt + (size_t)(c0 + 0) * P_ + p);
            float b = __ldcs(pt + (size_t)(c0 + 1) * P_ + p);
            half2 h = __floats2half2_rn(a, b);
            ow[j] = *reinterpret_cast<unsigned int*>(&h);
        }
        dst[hh] = o;
    }
}

// ---------------------------------------------------------------------------
// Kernel 2: quad-per-pixel compositor (fp16 gather, fp32 accumulate).
// 4 lanes per pixel; lane j owns channels [4j, 4j+4) = one 8B chunk.
// ---------------------------------------------------------------------------
__global__ void __launch_bounds__(256)
compositor_kernel(const int* __restrict__ frag,
                  const float* __restrict__ zbuf,
                  float* __restrict__ out) {
    __shared__ float s_out[64 * 17];   // [pixel][channel], pad -> conflict-free

    int tid = threadIdx.x;
    int q   = tid >> 2;                // block-local pixel 0..63
    int j   = tid & 3;                 // quad lane (channel group)

    int i  = blockIdx.x * 64 + q;      // global pixel; HW_ % 64 == 0
    int n  = i / HW_;
    int hw = i - n * HW_;
    size_t base = (size_t)n * K_ * HW_ + hw;

    // --- fragment indices (broadcast within quad) ---
    int fr[K_];
#pragma unroll
    for (int k = 0; k < K_; k++)
        fr[k] = __ldcs(frag + base + (size_t)k * HW_);

    // --- distributed softmax: lane j handles k = 2j, 2j+1 ---
    float z0 = __ldcs(zbuf + base + (size_t)(2 * j)     * HW_);
    float z1 = __ldcs(zbuf + base + (size_t)(2 * j + 1) * HW_);
    if (z0 < 0.0f) z0 = -0.0001f;
    if (z1 < 0.0f) z1 = -0.0001f;
    float i0 = 1.0f / (z0 + 1e-6f);
    float i1 = 1.0f / (z1 + 1e-6f);

    float m = fmaxf(i0, i1);
    m = fmaxf(m, __shfl_xor_sync(0xffffffffu, m, 1));
    m = fmaxf(m, __shfl_xor_sync(0xffffffffu, m, 2));

    float e0 = __expf(i0 - m);
    float e1 = __expf(i1 - m);
    float s  = e0 + e1;
    s += __shfl_xor_sync(0xffffffffu, s, 1);
    s += __shfl_xor_sync(0xffffffffu, s, 2);
    float inv = 1.0f / s;
    float w0 = e0 * inv;
    float w1 = e1 * inv;

    // --- cooperative gather (8B fp16 per lane) + weighted accumulate ---
    float4 acc = make_float4(0.f, 0.f, 0.f, 0.f);
#pragma unroll
    for (int k = 0; k < K_; k++) {
        int   src = (tid & ~3) | (k >> 1);
        float wk  = __shfl_sync(0xffffffffu, (k & 1) ? w1 : w0, src);
        const uint2* pp = reinterpret_cast<const uint2*>(
                              g_pt_h + (size_t)fr[k] * C_) + j;
        uint2 v = __ldg(pp);
        half2  h0 = *reinterpret_cast<half2*>(&v.x);
        half2  h1 = *reinterpret_cast<half2*>(&v.y);
        float2 f0 = __half22float2(h0);
        float2 f1 = __half22float2(h1);
        acc.x = fmaf(wk, f0.x, acc.x);
        acc.y = fmaf(wk, f0.y, acc.y);
        acc.z = fmaf(wk, f1.x, acc.z);
        acc.w = fmaf(wk, f1.y, acc.w);
    }

    // --- stage to smem, then coalesced global stores ---
    float* sp = s_out + q * 17 + j * 4;
    sp[0] = acc.x; sp[1] = acc.y; sp[2] = acc.z; sp[3] = acc.w;
    __syncthreads();

    int hw_base = hw - q;
    size_t ob = (size_t)n * C_ * HW_ + hw_base;
#pragma unroll
    for (int r = 0; r < 4; r++) {
        int idx = r * 256 + tid;
        int c   = idx >> 6;
        int px  = idx & 63;
        __stcs(out + ob + (size_t)c * HW_ + px, s_out[px * 17 + c]);
    }
}

extern "C" void kernel_launch(void* const* d_in, const int* in_sizes, int n_in,
                              void* d_out, int out_size) {
    const int*   fragments = (const int*)d_in[0];
    const float* zbuf      = (const float*)d_in[1];
    const float* ptclds    = (const float*)d_in[2];
    float*       out       = (float*)d_out;

    (void)in_sizes; (void)n_in; (void)out_size;

    {
        int threads = 256;
        int blocks  = (P_ + threads - 1) / threads;
        transpose_ptclds_kernel<<<blocks, threads>>>(ptclds);
    }
    {
        int threads = 256;
        int blocks  = NPIX / 64;
        compositor_kernel<<<blocks, threads>>>(fragments, zbuf, out);
    }
}